// round 7
// baseline (speedup 1.0000x reference)
#include <cuda_runtime.h>
#include <cub/cub.cuh>
#include <cstdint>

// Problem constants (B=4,H=8,S=1024,D=64)
#define BH 32
#define S 1024
#define D 64
#define N_ELE (BH * S * S)          // 33554432 = 2^25
#define SHIFT 9
#define NB (1u << (31 - SHIFT))     // 4M buckets
#define QPITCH 129                  // qk 128-wide tile pitch (mod 32 == 1)
#define AVP 65                      // av smem pitch

// Static device scratch (allocation-free rule: __device__ globals only)
__device__ float    g_score[N_ELE];      // signed cosine scores, row-major [BH*S, S]
__device__ float    g_w[N_ELE];          // final weights
__device__ unsigned g_hist[NB];          // bucket populations
__device__ unsigned g_cum[NB];           // exclusive scan of populations
__device__ float    g_wmag[NB];          // per-bucket weight magnitude
__device__ float    g_invq[BH * S];
__device__ float    g_invk[BH * S];
__device__ unsigned char g_scantemp[1u << 22];

// ---------------------------------------------------------------------------
// Stage 0: zero histogram (must be re-done every replay)
// ---------------------------------------------------------------------------
__global__ void zero_hist_kernel() {
    unsigned i = blockIdx.x * blockDim.x + threadIdx.x;
    reinterpret_cast<uint4*>(g_hist)[i] = make_uint4(0u, 0u, 0u, 0u);
}

// ---------------------------------------------------------------------------
// Stage 1: inverse lengths  inv = 1/(sqrt(sum sq)+1e-5), one warp per row
// ---------------------------------------------------------------------------
__global__ void norms_kernel(const float* __restrict__ q, const float* __restrict__ k) {
    int warp = (blockIdx.x * blockDim.x + threadIdx.x) >> 5;
    int lane = threadIdx.x & 31;
    if (warp >= 2 * BH * S) return;
    bool is_q = warp < BH * S;
    int row = is_q ? warp : warp - BH * S;
    const float* p = (is_q ? q : k) + (size_t)row * D;
    float v0 = p[lane], v1 = p[lane + 32];
    float s = v0 * v0 + v1 * v1;
    #pragma unroll
    for (int o = 16; o; o >>= 1) s += __shfl_xor_sync(0xffffffffu, s, o);
    if (lane == 0) (is_q ? g_invq : g_invk)[row] = 1.0f / (sqrtf(s) + 1e-5f);
}

// ---------------------------------------------------------------------------
// Stage 2: QK^T (fp32) -> signed scores (STG.128) + atomic bucket histogram
// 128x128 tile, 256 threads, 8x8 micro-tile, dynamic smem
// (unchanged from proven 625us round-6 version)
// ---------------------------------------------------------------------------
__global__ void qk_kernel(const float* __restrict__ Q, const float* __restrict__ K) {
    extern __shared__ float sm[];
    float* Qs = sm;                    // [64][QPITCH]  Qs[d][r]
    float* Ks = sm + 64 * QPITCH;      // [64][QPITCH]  Ks[d][c]
    int bh = blockIdx.z;
    int i0 = blockIdx.y * 128;
    int j0 = blockIdx.x * 128;
    const float* Qb = Q + ((size_t)bh * S + i0) * D;
    const float* Kb = K + ((size_t)bh * S + j0) * D;
    int tid = threadIdx.x;

    #pragma unroll
    for (int l = 0; l < 32; l++) {
        int idx = tid + l * 256;          // 0..8191
        int r = idx >> 6, d = idx & 63;
        Qs[d * QPITCH + r] = Qb[(size_t)r * D + d];
        Ks[d * QPITCH + r] = Kb[(size_t)r * D + d];
    }
    __syncthreads();

    int tx = tid & 15, ty = tid >> 4;     // 16x16 threads, 8x8 each
    float acc[8][8] = {};
    #pragma unroll 8
    for (int d = 0; d < 64; d++) {
        float a[8], b[8];
        const float* Qrow = &Qs[d * QPITCH + ty * 8];
        const float* Krow = &Ks[d * QPITCH + tx * 8];
        #pragma unroll
        for (int u = 0; u < 8; u++) a[u] = Qrow[u];
        #pragma unroll
        for (int u = 0; u < 8; u++) b[u] = Krow[u];
        #pragma unroll
        for (int r = 0; r < 8; r++)
            #pragma unroll
            for (int u = 0; u < 8; u++)
                acc[r][u] += a[r] * b[u];
    }

    float iq[8], ik[8];
    #pragma unroll
    for (int u = 0; u < 8; u++) {
        iq[u] = g_invq[bh * S + i0 + ty * 8 + u];
        ik[u] = g_invk[bh * S + j0 + tx * 8 + u];
    }
    #pragma unroll
    for (int r = 0; r < 8; r++) {
        unsigned row = (unsigned)(bh * S + i0 + ty * 8 + r);
        float s[8];
        #pragma unroll
        for (int u = 0; u < 8; u++) s[u] = acc[r][u] * iq[r] * ik[u];
        unsigned base = (row << 10) | (unsigned)(j0 + tx * 8);
        *reinterpret_cast<float4*>(&g_score[base]) =
            make_float4(s[0], s[1], s[2], s[3]);
        *reinterpret_cast<float4*>(&g_score[base + 4]) =
            make_float4(s[4], s[5], s[6], s[7]);
        #pragma unroll
        for (int u = 0; u < 8; u++) {
            unsigned key = __float_as_uint(s[u]) & 0x7fffffffu;
            atomicAdd(&g_hist[key >> SHIFT], 1u);
        }
    }
}

// ---------------------------------------------------------------------------
// Stage 4: per-bucket weight magnitude:  wmag = -log(midrank/(n-1) + 1/n)
// ---------------------------------------------------------------------------
__global__ void wmag_kernel() {
    unsigned b = blockIdx.x * blockDim.x + threadIdx.x;
    unsigned pop = g_hist[b];
    if (pop == 0u) { g_wmag[b] = 0.0f; return; }
    float rmid = (float)g_cum[b] + 0.5f * (float)(pop - 1u);
    float prob = fmaf(rmid, 1.0f / (float)(N_ELE - 1), 0x1p-25f);
    g_wmag[b] = -logf(prob);
}

// ---------------------------------------------------------------------------
// Stage 5: elementwise weights: w = sign(score) * wmag[bucket(|score|)]
// 8 elements/thread: batched loads -> 8 independent gathers -> batched stores
// ---------------------------------------------------------------------------
__global__ void weight_kernel() {
    unsigned i = (blockIdx.x * blockDim.x + threadIdx.x) * 8u;
    float4 s0 = *reinterpret_cast<const float4*>(&g_score[i]);
    float4 s1 = *reinterpret_cast<const float4*>(&g_score[i + 4]);
    float sv[8] = {s0.x, s0.y, s0.z, s0.w, s1.x, s1.y, s1.z, s1.w};
    float w[8];
    #pragma unroll
    for (int u = 0; u < 8; u++) {
        unsigned key = __float_as_uint(sv[u]) & 0x7fffffffu;
        w[u] = (key == 0u) ? 0.0f : copysignf(__ldg(&g_wmag[key >> SHIFT]), sv[u]);
    }
    *reinterpret_cast<float4*>(&g_w[i]) = make_float4(w[0], w[1], w[2], w[3]);
    *reinterpret_cast<float4*>(&g_w[i + 4]) = make_float4(w[4], w[5], w[6], w[7]);
}

// ---------------------------------------------------------------------------
// Stage 6: out = (W / rowsum(|W|)) @ V
// 128x64 tile, 128 threads, 8x8 micro-tile (FFMA-bound), dynamic smem
// ---------------------------------------------------------------------------
__global__ void __launch_bounds__(128)
av_kernel(const float* __restrict__ V, float* __restrict__ out) {
    extern __shared__ float sm[];
    float* Ws = sm;                     // [128][AVP]  Ws[r][kk]
    float* Vs = sm + 128 * AVP;         // [64][AVP]   Vs[kk][c]
    float* rsum = sm + 128 * AVP + 64 * AVP;  // [128]
    int bh = blockIdx.y;
    int i0 = blockIdx.x * 128;
    int tid = threadIdx.x;              // 128 threads
    int tx = tid & 7, ty = tid >> 3;    // 8 col-groups x 16 row-groups
    const float* Wb = g_w + ((size_t)(bh * S + i0)) * S;
    const float* Vb = V + (size_t)bh * S * D;

    float acc[8][8] = {};
    float rs[8] = {};
    for (int kt = 0; kt < S; kt += 64) {
        #pragma unroll 8
        for (int l = 0; l < 64; l++) {
            int idx = tid + l * 128;           // 0..8191
            int r = idx >> 6, c = idx & 63;
            Ws[r * AVP + c] = Wb[(size_t)r * S + kt + c];
        }
        #pragma unroll 8
        for (int l = 0; l < 32; l++) {
            int idx = tid + l * 128;           // 0..4095
            int r = idx >> 6, c = idx & 63;
            Vs[r * AVP + c] = Vb[(size_t)(kt + r) * D + c];
        }
        __syncthreads();
        #pragma unroll 4
        for (int kk = 0; kk < 64; kk++) {
            float a[8], b[8];
            const float* Vrow = &Vs[kk * AVP + tx * 8];
            #pragma unroll
            for (int u = 0; u < 8; u++) b[u] = Vrow[u];
            #pragma unroll
            for (int r = 0; r < 8; r++) a[r] = Ws[(ty * 8 + r) * AVP + kk];
            if (tx == 0) {
                #pragma unroll
                for (int r = 0; r < 8; r++) rs[r] += fabsf(a[r]);
            }
            #pragma unroll
            for (int r = 0; r < 8; r++)
                #pragma unroll
                for (int u = 0; u < 8; u++)
                    acc[r][u] += a[r] * b[u];
        }
        __syncthreads();
    }
    if (tx == 0) {
        #pragma unroll
        for (int r = 0; r < 8; r++) rsum[ty * 8 + r] = rs[r];
    }
    __syncthreads();
    #pragma unroll
    for (int r = 0; r < 8; r++) {
        float inv = 1.0f / rsum[ty * 8 + r];
        size_t obase = ((size_t)(bh * S) + i0 + ty * 8 + r) * D + tx * 8;
        #pragma unroll
        for (int u = 0; u < 8; u++)
            out[obase + u] = acc[r][u] * inv;
    }
}

// ---------------------------------------------------------------------------
extern "C" void kernel_launch(void* const* d_in, const int* in_sizes, int n_in,
                              void* d_out, int out_size) {
    const float* q = (const float*)d_in[0];
    const float* k = (const float*)d_in[1];
    const float* v = (const float*)d_in[2];
    float* out = (float*)d_out;

    // Stage 0: zero histogram (4M words, uint4 stores)
    zero_hist_kernel<<<NB / 1024, 256>>>();

    // Stage 1: inverse lengths
    norms_kernel<<<8192, 256>>>(q, k);

    // Stage 2: cosine scores + bucket histogram (128x128 tiles, 66KB dyn smem)
    const int qk_smem = 2 * 64 * QPITCH * sizeof(float);
    cudaFuncSetAttribute(qk_kernel, cudaFuncAttributeMaxDynamicSharedMemorySize,
                         qk_smem);
    dim3 g1(S / 128, S / 128, BH);
    qk_kernel<<<g1, 256, qk_smem>>>(q, k);

    // Stage 3: exclusive scan of bucket populations
    unsigned *hist_p, *cum_p;
    void* tmp;
    cudaGetSymbolAddress((void**)&hist_p, g_hist);
    cudaGetSymbolAddress((void**)&cum_p, g_cum);
    cudaGetSymbolAddress(&tmp, g_scantemp);
    size_t temp_bytes = 0;
    cub::DeviceScan::ExclusiveSum(nullptr, temp_bytes, hist_p, cum_p, (int)NB);
    if (temp_bytes > sizeof(g_scantemp)) return;
    cub::DeviceScan::ExclusiveSum(tmp, temp_bytes, hist_p, cum_p, (int)NB);

    // Stage 4: per-bucket weight magnitudes
    wmag_kernel<<<NB / 256, 256>>>();

    // Stage 5: elementwise weights (streaming, 8 elems/thread)
    weight_kernel<<<N_ELE / 2048, 256>>>();

    // Stage 6: row-L1-normalize + apply to V (128x64 tiles, ~50KB dyn smem)
    const int av_smem = (128 * AVP + 64 * AVP + 128) * sizeof(float);
    cudaFuncSetAttribute(av_kernel, cudaFuncAttributeMaxDynamicSharedMemorySize,
                         av_smem);
    dim3 g2(S / 128, BH);
    av_kernel<<<g2, 128, av_smem>>>(v, out);
}